// round 15
// baseline (speedup 1.0000x reference)
#include <cuda_runtime.h>
#include <cuda_fp16.h>
#include <math.h>

#define D 128
#define NMAX 210048
#define SAH 68   // A-tile row stride in half2 words (272B); 68 % 32 == 4 -> conflict-free ldmatrix

// Scratch: Q, K, V in fp16
__device__ float g_scr[(size_t)4 * NMAX * D / 2 + 1024];
__device__ uint2 g_wpackh[4 * 8 * 16 * 32];   // fp16 m16n8k16 B fragments, 32KB/matrix
__device__ int g_ws16[20002];
__device__ int g_ws64[8002];

__device__ __forceinline__ __half2 u2h(unsigned u) { return *(__half2*)&u; }

// ---------------------------------------------------------------------------
__global__ void build_ws(const int* __restrict__ fp, int n, int L,
                         int* __restrict__ ws, int nw)
{
    int i = blockIdx.x * blockDim.x + threadIdx.x;
    if (i < n) {
        int w = fp[i] / L;
        if (i == 0 || fp[i - 1] / L != w) ws[w] = i;
    }
    if (i == 0) ws[nw] = n;
}

// ---------------------------------------------------------------------------
// Pack W into m16n8k16 fp16 B-fragment order.
// ---------------------------------------------------------------------------
__global__ void pack_w(const float* __restrict__ Win, const float* __restrict__ Wout)
{
    int i = blockIdx.x * blockDim.x + threadIdx.x;   // 0..16383
    if (i >= 4 * 8 * 16 * 32) return;
    int lane = i & 31;
    int nf = (i >> 5) & 15;
    int ks = (i >> 9) & 7;
    int m  = i >> 12;
    int g = lane >> 2, t4 = lane & 3;
    const float* W = (m < 3) ? (Win + (size_t)m * D * D) : Wout;
    int n  = nf * 8 + g;
    int k0 = ks * 16 + 2 * t4;
    __half2 b0 = __floats2half2_rn(W[n * D + k0],     W[n * D + k0 + 1]);
    __half2 b1 = __floats2half2_rn(W[n * D + k0 + 8], W[n * D + k0 + 9]);
    uint2 out;
    out.x = *(unsigned*)&b0;
    out.y = *(unsigned*)&b1;
    g_wpackh[i] = out;
}

// ---------------------------------------------------------------------------
// FP16 tensor-core QKV GEMM (m16n8k16, fp32 accum); A-frags via ldmatrix.x4.
// Staged coalesced epilogue. (Same as round 14; only the NM=3 path is used.)
// ---------------------------------------------------------------------------
template <bool ADD_POS, int NM, bool GATHER>
__global__ __launch_bounds__(256, 4)
void gemm_mma(const void* __restrict__ Xv,
              const int* __restrict__ g16, const int* __restrict__ g64,
              const float* __restrict__ pos16, const float* __restrict__ pos64,
              const int* __restrict__ fp16x, const int* __restrict__ fp64x,
              int wmat, const float* __restrict__ bias,
              void* __restrict__ O0, void* __restrict__ O1, void* __restrict__ O2,
              int n16, int ntok)
{
    extern __shared__ unsigned smu[];
    unsigned* As = smu;
    unsigned* Ar = (NM == 3) ? smu + 64 * SAH : smu;
    unsigned* stg = smu + (NM == 3 ? 2 : 1) * 64 * SAH;
    const int tid = threadIdx.x;
    const int tb = blockIdx.x * 64;

#pragma unroll
    for (int it = 0; it < 8; it++) {
        int idx = tid + it * 256;
        int r  = idx >> 5;
        int c4 = (idx & 31) << 2;
        int tk = tb + r;
        int wi = r * SAH + (c4 >> 1);
        const float* X = (const float*)Xv;
        float4 v = make_float4(0.f, 0.f, 0.f, 0.f);
        float4 vp = v;
        if (tk < ntok) {
            bool gA = tk < n16;
            int src = GATHER ? (gA ? g16[tk] : g64[tk - n16]) : tk;
            v = *(const float4*)(X + (size_t)src * D + c4);
            vp = v;
            if (ADD_POS) {
                const float* P = gA ? pos16 : pos64;
                int f = gA ? fp16x[tk] : fp64x[tk - n16];
                float4 p = *(const float4*)(P + (size_t)f * D + c4);
                vp.x += p.x; vp.y += p.y; vp.z += p.z; vp.w += p.w;
            }
        }
        {
            __half2 h0 = __floats2half2_rn(vp.x, vp.y);
            __half2 h1 = __floats2half2_rn(vp.z, vp.w);
            uint2 st; st.x = *(unsigned*)&h0; st.y = *(unsigned*)&h1;
            *(uint2*)(As + wi) = st;
        }
        if (NM == 3) {
            __half2 h0 = __floats2half2_rn(v.x, v.y);
            __half2 h1 = __floats2half2_rn(v.z, v.w);
            uint2 st; st.x = *(unsigned*)&h0; st.y = *(unsigned*)&h1;
            *(uint2*)(Ar + wi) = st;
        }
    }
    __syncthreads();

    const int w  = tid >> 5, lane = tid & 31;
    const int wm = w & 1,  wn = w >> 1;
    const int g  = lane >> 2, t4 = lane & 3;

    unsigned a_base;
    {
        int rowp = wm * 32 + (lane & 7) + ((lane >> 3) & 1) * 8;
        int colw = (lane >> 4) * 4;
        a_base = (unsigned)__cvta_generic_to_shared(As + rowp * SAH + colw);
    }

#pragma unroll
    for (int m = 0; m < NM; m++) {
        const unsigned ab = a_base + ((NM == 3 && m == 2) ? 64 * SAH * 4 : 0);
        float acc[2][4][4];
#pragma unroll
        for (int ma = 0; ma < 2; ma++)
#pragma unroll
            for (int nf = 0; nf < 4; nf++)
#pragma unroll
                for (int e = 0; e < 4; e++) acc[ma][nf][e] = 0.f;

        const uint2* bp = g_wpackh + ((size_t)(wmat + m) * 8 * 16 + wn * 4) * 32 + lane;

#pragma unroll
        for (int ks = 0; ks < 8; ks++) {
            unsigned a[2][4];
#pragma unroll
            for (int ma = 0; ma < 2; ma++) {
                asm volatile(
                    "ldmatrix.sync.aligned.m8n8.x4.shared.b16 {%0,%1,%2,%3}, [%4];"
                    : "=r"(a[ma][0]), "=r"(a[ma][1]), "=r"(a[ma][2]), "=r"(a[ma][3])
                    : "r"(ab + ma * 16 * SAH * 4 + ks * 32));
            }
#pragma unroll
            for (int nf = 0; nf < 4; nf++) {
                uint2 bv = __ldg(bp + (ks * 16 + nf) * 32);
#pragma unroll
                for (int ma = 0; ma < 2; ma++) {
                    asm volatile(
                        "mma.sync.aligned.m16n8k16.row.col.f32.f16.f16.f32 "
                        "{%0,%1,%2,%3}, {%4,%5,%6,%7}, {%8,%9}, {%0,%1,%2,%3};"
                        : "+f"(acc[ma][nf][0]), "+f"(acc[ma][nf][1]),
                          "+f"(acc[ma][nf][2]), "+f"(acc[ma][nf][3])
                        : "r"(a[ma][0]), "r"(a[ma][1]), "r"(a[ma][2]), "r"(a[ma][3]),
                          "r"(bv.x), "r"(bv.y));
                }
            }
        }

        const float* bm = bias + m * D;
#pragma unroll
        for (int ma = 0; ma < 2; ma++) {
#pragma unroll
            for (int rr = 0; rr < 2; rr++) {
                int row = wm * 32 + ma * 16 + g + rr * 8;
#pragma unroll
                for (int nf = 0; nf < 4; nf++) {
                    int c = wn * 32 + nf * 8 + 2 * t4;
                    float2 bi = *(const float2*)(bm + c);
                    float vx = acc[ma][nf][rr * 2 + 0] + bi.x;
                    float vy = acc[ma][nf][rr * 2 + 1] + bi.y;
                    __half2 hv = __floats2half2_rn(vx, vy);
                    stg[row * SAH + wn * 16 + nf * 4 + t4] = *(unsigned*)&hv;
                }
            }
        }
        __syncthreads();

        void* OUT = (m == 0) ? O0 : (m == 1) ? O1 : O2;
#pragma unroll
        for (int it = 0; it < 4; it++) {
            int idx = tid + it * 256;
            int row = idx >> 4, q = idx & 15;
            int r = tb + row;
            if (r < ntok) {
                uint4 v = *(const uint4*)(stg + row * SAH + q * 4);
                *(uint4*)((__half*)OUT + (size_t)r * D + q * 8) = v;
            }
        }
        if (m + 1 < NM) __syncthreads();
    }
}

// ---------------------------------------------------------------------------
__device__ __forceinline__ void h8_to_f(const uint4& u, float* f) {
    float2 a = __half22float2(*(const __half2*)&u.x); f[0] = a.x; f[1] = a.y;
    float2 b = __half22float2(*(const __half2*)&u.y); f[2] = b.x; f[3] = b.y;
    float2 c = __half22float2(*(const __half2*)&u.z); f[4] = c.x; f[5] = c.y;
    float2 d = __half22float2(*(const __half2*)&u.w); f[6] = d.x; f[7] = d.y;
}

__device__ __forceinline__ float dot16h(const uint4& qa, const uint4& qb,
                                        const uint4& ka, const uint4& kb) {
    __half2 t = __hmul2(u2h(qa.x), u2h(ka.x));
    t = __hfma2(u2h(qa.y), u2h(ka.y), t);
    t = __hfma2(u2h(qa.z), u2h(ka.z), t);
    t = __hfma2(u2h(qa.w), u2h(ka.w), t);
    __half2 s = __hmul2(u2h(qb.x), u2h(kb.x));
    s = __hfma2(u2h(qb.y), u2h(kb.y), s);
    s = __hfma2(u2h(qb.z), u2h(kb.z), s);
    s = __hfma2(u2h(qb.w), u2h(kb.w), s);
    float2 f = __half22float2(__hadd2(t, s));
    return f.x + f.y;
}

// write one query's 16 output channels (scaled) into the fp16 A-tile
__device__ __forceinline__ void store_row(unsigned* As, int row, int h,
                                          const float* acc, float inv) {
#pragma unroll
    for (int e = 0; e < 8; e++) {
        __half2 hv = __floats2half2_rn(acc[2 * e] * inv, acc[2 * e + 1] * inv);
        As[row * SAH + h * 8 + e] = *(unsigned*)&hv;
    }
}

// ---------------------------------------------------------------------------
// Out-projection tail: 256 threads, A (<=64 rows) in smem fp16 tile, B = Wout
// fragments from L1-resident g_wpackh, fp32 staged epilogue scattered via vox.
// ---------------------------------------------------------------------------
__device__ __forceinline__ void proj_tail(
    unsigned* As, float* sf, const int* __restrict__ vox,
    const float* __restrict__ bias, float* __restrict__ out,
    int tb, int len_total, int tid)
{
    const int w  = tid >> 5, lane = tid & 31;
    const int wm = w & 1,  wn = w >> 1;
    const int g  = lane >> 2, t4 = lane & 3;
    unsigned a_base;
    {
        int rowp = wm * 32 + (lane & 7) + ((lane >> 3) & 1) * 8;
        int colw = (lane >> 4) * 4;
        a_base = (unsigned)__cvta_generic_to_shared(As + rowp * SAH + colw);
    }
    float acc[2][4][4];
#pragma unroll
    for (int ma = 0; ma < 2; ma++)
#pragma unroll
        for (int nf = 0; nf < 4; nf++)
#pragma unroll
            for (int e = 0; e < 4; e++) acc[ma][nf][e] = 0.f;

    const uint2* bp = g_wpackh + ((size_t)3 * 8 * 16 + wn * 4) * 32 + lane;

#pragma unroll
    for (int ks = 0; ks < 8; ks++) {
        unsigned a[2][4];
#pragma unroll
        for (int ma = 0; ma < 2; ma++) {
            asm volatile(
                "ldmatrix.sync.aligned.m8n8.x4.shared.b16 {%0,%1,%2,%3}, [%4];"
                : "=r"(a[ma][0]), "=r"(a[ma][1]), "=r"(a[ma][2]), "=r"(a[ma][3])
                : "r"(a_base + ma * 16 * SAH * 4 + ks * 32));
        }
#pragma unroll
        for (int nf = 0; nf < 4; nf++) {
            uint2 bv = __ldg(bp + (ks * 16 + nf) * 32);
#pragma unroll
            for (int ma = 0; ma < 2; ma++) {
                asm volatile(
                    "mma.sync.aligned.m16n8k16.row.col.f32.f16.f16.f32 "
                    "{%0,%1,%2,%3}, {%4,%5,%6,%7}, {%8,%9}, {%0,%1,%2,%3};"
                    : "+f"(acc[ma][nf][0]), "+f"(acc[ma][nf][1]),
                      "+f"(acc[ma][nf][2]), "+f"(acc[ma][nf][3])
                    : "r"(a[ma][0]), "r"(a[ma][1]), "r"(a[ma][2]), "r"(a[ma][3]),
                      "r"(bv.x), "r"(bv.y));
            }
        }
    }

    // fp32 stage (stride 140 floats; banks 12g+2t4 distinct)
    float2* sfp = (float2*)sf;
#pragma unroll
    for (int ma = 0; ma < 2; ma++) {
#pragma unroll
        for (int rr = 0; rr < 2; rr++) {
            int row = wm * 32 + ma * 16 + g + rr * 8;
#pragma unroll
            for (int nf = 0; nf < 4; nf++) {
                int c = wn * 32 + nf * 8 + 2 * t4;
                float2 bi = *(const float2*)(bias + c);
                sfp[row * 70 + wn * 16 + nf * 4 + t4] =
                    make_float2(acc[ma][nf][rr * 2 + 0] + bi.x,
                                acc[ma][nf][rr * 2 + 1] + bi.y);
            }
        }
    }
    __syncthreads();

    // coalesced scattered row copies
#pragma unroll
    for (int it = 0; it < 8; it++) {
        int idx = tid + it * 256;
        int row = idx >> 5, q = idx & 31;
        if (row < len_total) {
            int rowg = vox[tb + row];
            uint4 v = *(const uint4*)(sf + row * 140 + q * 4);
            *(uint4*)(out + (size_t)rowg * D + q * 4) = v;
        }
    }
}

// ---------------------------------------------------------------------------
// Fused s16 attention + out-projection: 4 windows/block (contiguous <=64 toks).
// ---------------------------------------------------------------------------
__global__ __launch_bounds__(256)
void attn_proj16(const __half* __restrict__ Q, const __half* __restrict__ K,
                 const __half* __restrict__ V, const int* __restrict__ ws,
                 const int* __restrict__ vox, const float* __restrict__ bias,
                 float* __restrict__ out, int nw)
{
    constexpr int L = 16;
    extern __shared__ char smc[];
    uint4* kv = (uint4*)smc;                        // 4 windows x 2 x 16 x 16 uint4 (32KB)
    unsigned* As = (unsigned*)(smc + 35840);        // 64 x SAH fp16 tile
    float* sf = (float*)smc;                        // fp32 stage aliases kv (35840B)
    const int tid = threadIdx.x;
    const int w0 = blockIdx.x * 4;
    const int tb = ws[w0];
    const int wend = min(w0 + 4, nw);
    const int len_total = ws[wend] - tb;

    const int wl = tid >> 6;                        // window slot 0..3
    const int w  = w0 + wl;
    uint4* Ks = kv + wl * (2 * L * 16);
    uint4* Vs = Ks + L * 16;
    int t0 = tb, len = 0;
    if (w < nw) { t0 = ws[w]; len = ws[w + 1] - t0; }

    const int lt = tid & 63;
    for (int idx = lt; idx < len * 16; idx += 64) {
        int j = idx >> 4, gg = idx & 15;
        int h = gg >> 1, p = gg & 1;
        Ks[j * 16 + (p * 8 + h)] = ((const uint4*)K)[(size_t)(t0 + j) * 16 + gg];
        Vs[j * 16 + (p * 8 + h)] = ((const uint4*)V)[(size_t)(t0 + j) * 16 + gg];
    }
    __syncthreads();

    const int qs = lt >> 3;
    const int h  = lt & 7;
    const int q0 = 2 * qs, q1 = q0 + 1;
    const bool act = (w < nw) && (q0 < len);

    if (act) {
        const bool v1 = (q1 < len);
        uint4 qa0, qb0, qa1, qb1;
        {
            const uint4* Qp0 = (const uint4*)Q + (size_t)(t0 + q0) * 16 + h * 2;
            const uint4* Qp1 = (const uint4*)Q + (size_t)(t0 + (v1 ? q1 : q0)) * 16 + h * 2;
            qa0 = Qp0[0]; qb0 = Qp0[1];
            qa1 = Qp1[0]; qb1 = Qp1[1];
        }
        float s0[L], s1[L];
        float m0 = -1e30f, m1 = -1e30f;
#pragma unroll
        for (int j = 0; j < L; j++) {
            bool kvv = j < len;
            int key = kvv ? j : 0;
            uint4 ka = Ks[key * 16 + h], kb = Ks[key * 16 + 8 + h];
            float a = dot16h(qa0, qb0, ka, kb);
            float b = dot16h(qa1, qb1, ka, kb);
            s0[j] = kvv ? a : -1e30f;
            s1[j] = kvv ? b : -1e30f;
            m0 = fmaxf(m0, s0[j]); m1 = fmaxf(m1, s1[j]);
        }
        float d0 = 0.f, d1 = 0.f;
        float acc0[16], acc1[16];
#pragma unroll
        for (int e = 0; e < 16; e++) { acc0[e] = 0.f; acc1[e] = 0.f; }
#pragma unroll
        for (int j = 0; j < L; j++) {
            if (j >= len) break;
            float p0 = __expf((s0[j] - m0) * 0.25f);
            float p1 = __expf((s1[j] - m1) * 0.25f);
            d0 += p0; d1 += p1;
            float vf[16];
            h8_to_f(Vs[j * 16 + h], vf); h8_to_f(Vs[j * 16 + 8 + h], vf + 8);
#pragma unroll
            for (int e = 0; e < 16; e++) {
                acc0[e] += p0 * vf[e];
                acc1[e] += p1 * vf[e];
            }
        }
        store_row(As, t0 - tb + q0, h, acc0, 1.f / d0);
        if (v1) store_row(As, t0 - tb + q1, h, acc1, 1.f / d1);
    }
    __syncthreads();

    proj_tail(As, sf, vox, bias, out, tb, len_total, tid);
}

// ---------------------------------------------------------------------------
// Fused s64 attention + out-projection: 1 window/block, 256 threads,
// 2 queries/thread, 16-key chunked online softmax.
// ---------------------------------------------------------------------------
__global__ __launch_bounds__(256)
void attn_proj64(const __half* __restrict__ Q, const __half* __restrict__ K,
                 const __half* __restrict__ V, const int* __restrict__ ws,
                 const int* __restrict__ vox, const float* __restrict__ bias,
                 float* __restrict__ out, int nw)
{
    constexpr int L = 64;
    extern __shared__ char smc[];
    uint4* Ks = (uint4*)smc;
    uint4* Vs = Ks + L * 16;
    unsigned* As = (unsigned*)(smc + 35840);
    float* sf = (float*)smc;
    const int tid = threadIdx.x;
    const int w = blockIdx.x;
    const int t0 = ws[w];
    const int len = ws[w + 1] - t0;

    for (int idx = tid; idx < len * 16; idx += 256) {
        int j = idx >> 4, gg = idx & 15;
        int h = gg >> 1, p = gg & 1;
        Ks[j * 16 + (p * 8 + h)] = ((const uint4*)K)[(size_t)(t0 + j) * 16 + gg];
        Vs[j * 16 + (p * 8 + h)] = ((const uint4*)V)[(size_t)(t0 + j) * 16 + gg];
    }
    __syncthreads();

    const int qs = tid >> 3;
    const int h  = tid & 7;
    const int q0 = 2 * qs, q1 = q0 + 1;
    const bool act = (q0 < len);

    if (act) {
        const bool v1 = (q1 < len);
        uint4 qa0, qb0, qa1, qb1;
        {
            const uint4* Qp0 = (const uint4*)Q + (size_t)(t0 + q0) * 16 + h * 2;
            const uint4* Qp1 = (const uint4*)Q + (size_t)(t0 + (v1 ? q1 : q0)) * 16 + h * 2;
            qa0 = Qp0[0]; qb0 = Qp0[1];
            qa1 = Qp1[0]; qb1 = Qp1[1];
        }
        float m0 = -1e30f, m1 = -1e30f, d0 = 0.f, d1 = 0.f;
        float acc0[16], acc1[16];
#pragma unroll
        for (int e = 0; e < 16; e++) { acc0[e] = 0.f; acc1[e] = 0.f; }

        for (int c0 = 0; c0 < len; c0 += 16) {
            float s0[16], s1[16];
#pragma unroll
            for (int j = 0; j < 16; j++) {
                if (c0 + j >= len) { s0[j] = -1e30f; s1[j] = -1e30f; continue; }
                uint4 ka = Ks[(c0 + j) * 16 + h], kb = Ks[(c0 + j) * 16 + 8 + h];
                s0[j] = dot16h(qa0, qb0, ka, kb);
                s1[j] = dot16h(qa1, qb1, ka, kb);
            }
            float cm0 = s0[0], cm1 = s1[0];
#pragma unroll
            for (int j = 1; j < 16; j++) { cm0 = fmaxf(cm0, s0[j]); cm1 = fmaxf(cm1, s1[j]); }
            float mn0 = fmaxf(m0, cm0), mn1 = fmaxf(m1, cm1);
            float sc0 = __expf((m0 - mn0) * 0.25f);
            float sc1 = __expf((m1 - mn1) * 0.25f);
            m0 = mn0; m1 = mn1;
            d0 *= sc0; d1 *= sc1;
#pragma unroll
            for (int e = 0; e < 16; e++) { acc0[e] *= sc0; acc1[e] *= sc1; }

#pragma unroll
            for (int j = 0; j < 16; j++) {
                if (c0 + j >= len) break;
                float p0 = __expf((s0[j] - m0) * 0.25f);
                float p1 = __expf((s1[j] - m1) * 0.25f);
                d0 += p0; d1 += p1;
                float vf[16];
                h8_to_f(Vs[(c0 + j) * 16 + h], vf);
                h8_to_f(Vs[(c0 + j) * 16 + 8 + h], vf + 8);
#pragma unroll
                for (int e = 0; e < 16; e++) {
                    acc0[e] += p0 * vf[e];
                    acc1[e] += p1 * vf[e];
                }
            }
        }
        store_row(As, q0, h, acc0, 1.f / d0);
        if (v1) store_row(As, q1, h, acc1, 1.f / d1);
    }
    __syncthreads();

    proj_tail(As, sf, vox, bias, out, t0, len, tid);
}

// ---------------------------------------------------------------------------
extern "C" void kernel_launch(void* const* d_in, const int* in_sizes, int n_in,
                              void* d_out, int out_size)
{
    const float* feat  = (const float*)d_in[0];
    const float* pos16 = (const float*)d_in[1];
    const float* pos64 = (const float*)d_in[2];
    const float* Win   = (const float*)d_in[3];
    const float* bin   = (const float*)d_in[4];
    const float* Wout  = (const float*)d_in[5];
    const float* bout  = (const float*)d_in[6];
    const int* vox16 = (const int*)d_in[7];
    const int* fp16i = (const int*)d_in[8];
    const int* vox64 = (const int*)d_in[9];
    const int* fp64i = (const int*)d_in[10];
    const int n16  = in_sizes[7];
    const int n64  = in_sizes[9];
    const int nw16 = in_sizes[1] / (16 * D);
    const int nw64 = in_sizes[2] / (64 * D);
    const int ntok = n16 + n64;
    float* out = (float*)d_out;

    float* scr = nullptr;
    cudaGetSymbolAddress((void**)&scr, g_scr);
    int* ws16 = nullptr; cudaGetSymbolAddress((void**)&ws16, g_ws16);
    int* ws64 = nullptr; cudaGetSymbolAddress((void**)&ws64, g_ws64);
    __half* Qh = (__half*)scr;
    __half* Kh = Qh + (size_t)NMAX * D;
    __half* Vh = Qh + (size_t)2 * NMAX * D;

    const size_t ATILE = (size_t)64 * SAH * sizeof(unsigned);       // 17408
    const size_t gsm3  = 3 * ATILE;                                 // QKV: 2 tiles + fp16 stage
    const size_t fsm   = 35840 + ATILE;                             // fused attn+proj: 53248
    cudaFuncSetAttribute((const void*)gemm_mma<true, 3, true>,
                         cudaFuncAttributeMaxDynamicSharedMemorySize, (int)gsm3);
    cudaFuncSetAttribute((const void*)attn_proj16,
                         cudaFuncAttributeMaxDynamicSharedMemorySize, (int)fsm);
    cudaFuncSetAttribute((const void*)attn_proj64,
                         cudaFuncAttributeMaxDynamicSharedMemorySize, (int)fsm);

    build_ws<<<(n16 + 255) / 256, 256>>>(fp16i, n16, 16, ws16, nw16);
    build_ws<<<(n64 + 255) / 256, 256>>>(fp64i, n64, 64, ws64, nw64);
    pack_w<<<64, 256>>>(Win, Wout);

    const int gt = (ntok + 63) / 64;
    const size_t off = (size_t)n16 * D;

    // Fused Q+K+V over BOTH groups: one gather, three matrices, fp16 outputs.
    gemm_mma<true, 3, true><<<gt, 256, gsm3>>>(
        feat, vox16, vox64, pos16, pos64, fp16i, fp64i, 0, bin,
        Qh, Kh, Vh, n16, ntok);

    // Fused attention + out-projection, scattered straight into d_out.
    attn_proj16<<<(nw16 + 3) / 4, 256, fsm>>>(Qh, Kh, Vh, ws16, vox16, bout, out, nw16);
    attn_proj64<<<nw64, 256, fsm>>>(Qh + off, Kh + off, Vh + off, ws64, vox64, bout, out, nw64);
}

// round 17
// speedup vs baseline: 1.0742x; 1.0742x over previous
#include <cuda_runtime.h>
#include <cuda_fp16.h>
#include <math.h>

#define D 128
#define NMAX 210048
#define SAH 68   // A-tile row stride in half2 words (272B); 68 % 32 == 4 -> conflict-free ldmatrix

// Scratch: Q, K, V, attention-out in fp16
__device__ float g_scr[(size_t)4 * NMAX * D / 2 + 1024];
__device__ uint2 g_wpackh[4 * 8 * 16 * 32];   // fp16 m16n8k16 B fragments, 32KB/matrix
__device__ int g_ws16[20002];
__device__ int g_ws64[8002];

__device__ __forceinline__ __half2 u2h(unsigned u) { return *(__half2*)&u; }

// ---------------------------------------------------------------------------
// Window-start builder for BOTH groups in one launch.
// ---------------------------------------------------------------------------
__global__ void build_ws2(const int* __restrict__ fpA, int nA, int nwA, int* __restrict__ wsA,
                          const int* __restrict__ fpB, int nB, int nwB, int* __restrict__ wsB)
{
    int i = blockIdx.x * blockDim.x + threadIdx.x;
    if (i < nA) {
        int w = fpA[i] / 16;
        if (i == 0 || fpA[i - 1] / 16 != w) wsA[w] = i;
    } else if (i < nA + nB) {
        int k = i - nA;
        int w = fpB[k] / 64;
        if (k == 0 || fpB[k - 1] / 64 != w) wsB[w] = k;
    }
    if (i == 0) { wsA[nwA] = nA; wsB[nwB] = nB; }
}

// ---------------------------------------------------------------------------
// Pack W into m16n8k16 fp16 B-fragment order.
// ---------------------------------------------------------------------------
__global__ void pack_w(const float* __restrict__ Win, const float* __restrict__ Wout)
{
    int i = blockIdx.x * blockDim.x + threadIdx.x;   // 0..16383
    if (i >= 4 * 8 * 16 * 32) return;
    int lane = i & 31;
    int nf = (i >> 5) & 15;
    int ks = (i >> 9) & 7;
    int m  = i >> 12;
    int g = lane >> 2, t = lane & 3;
    const float* W = (m < 3) ? (Win + (size_t)m * D * D) : Wout;
    int n  = nf * 8 + g;
    int k0 = ks * 16 + 2 * t;
    __half2 b0 = __floats2half2_rn(W[n * D + k0],     W[n * D + k0 + 1]);
    __half2 b1 = __floats2half2_rn(W[n * D + k0 + 8], W[n * D + k0 + 9]);
    uint2 out;
    out.x = *(unsigned*)&b0;
    out.y = *(unsigned*)&b1;
    g_wpackh[i] = out;
}

// ---------------------------------------------------------------------------
// FP16 tensor-core GEMM (m16n8k16, fp32 accum); A-frags via ldmatrix.x4.
//   STAGED: epilogue routed through smem for coalesced 16B stores (QKV path).
//   !STAGED: direct per-fragment stores (proj path).
// ---------------------------------------------------------------------------
template <bool ADD_POS, int NM, bool GATHER, bool SCATTER, bool HIN, bool HOUT, bool STAGED>
__global__ __launch_bounds__(256, 4)
void gemm_mma(const void* __restrict__ Xv,
              const int* __restrict__ g16, const int* __restrict__ g64,
              const float* __restrict__ pos16, const float* __restrict__ pos64,
              const int* __restrict__ fp16x, const int* __restrict__ fp64x,
              int wmat, const float* __restrict__ bias,
              void* __restrict__ O0, void* __restrict__ O1, void* __restrict__ O2,
              const int* __restrict__ s16, const int* __restrict__ s64,
              int n16, int ntok)
{
    extern __shared__ unsigned smu[];                 // A tiles as half2 words
    unsigned* As = smu;                               // 64 x SAH  (pos-added / only)
    unsigned* Ar = (NM == 3) ? smu + 64 * SAH : smu;  // raw tile (V operand)
    unsigned* stg = smu + (NM == 3 ? 2 : 1) * 64 * SAH;  // output stage (STAGED only)
    const int tid = threadIdx.x;
    const int tb = blockIdx.x * 64;

    // Stage A
#pragma unroll
    for (int it = 0; it < 8; it++) {
        int idx = tid + it * 256;
        int r  = idx >> 5;
        int c4 = (idx & 31) << 2;
        int tk = tb + r;
        int wi = r * SAH + (c4 >> 1);
        if (HIN) {
            uint2 st = make_uint2(0u, 0u);
            if (tk < ntok) {
                const unsigned* Xh = (const unsigned*)Xv;
                st = *(const uint2*)(Xh + (size_t)tk * 64 + (c4 >> 1));
            }
            *(uint2*)(As + wi) = st;
        } else {
            const float* X = (const float*)Xv;
            float4 v = make_float4(0.f, 0.f, 0.f, 0.f);
            float4 vp = v;
            if (tk < ntok) {
                bool gA = tk < n16;
                int src = GATHER ? (gA ? g16[tk] : g64[tk - n16]) : tk;
                v = *(const float4*)(X + (size_t)src * D + c4);
                vp = v;
                if (ADD_POS) {
                    const float* P = gA ? pos16 : pos64;
                    int f = gA ? fp16x[tk] : fp64x[tk - n16];
                    float4 p = *(const float4*)(P + (size_t)f * D + c4);
                    vp.x += p.x; vp.y += p.y; vp.z += p.z; vp.w += p.w;
                }
            }
            {
                __half2 h0 = __floats2half2_rn(vp.x, vp.y);
                __half2 h1 = __floats2half2_rn(vp.z, vp.w);
                uint2 st; st.x = *(unsigned*)&h0; st.y = *(unsigned*)&h1;
                *(uint2*)(As + wi) = st;
            }
            if (NM == 3) {
                __half2 h0 = __floats2half2_rn(v.x, v.y);
                __half2 h1 = __floats2half2_rn(v.z, v.w);
                uint2 st; st.x = *(unsigned*)&h0; st.y = *(unsigned*)&h1;
                *(uint2*)(Ar + wi) = st;
            }
        }
    }
    __syncthreads();

    const int w  = tid >> 5, lane = tid & 31;
    const int wm = w & 1,  wn = w >> 1;
    const int g  = lane >> 2, t4 = lane & 3;

    // ldmatrix.x4 source address (a0..a3 fragment order for m16n8k16.row)
    unsigned a_base;
    {
        int rowp = wm * 32 + (lane & 7) + ((lane >> 3) & 1) * 8;
        int colw = (lane >> 4) * 4;
        a_base = (unsigned)__cvta_generic_to_shared(As + rowp * SAH + colw);
    }

#pragma unroll
    for (int m = 0; m < NM; m++) {
        const unsigned ab = a_base + ((NM == 3 && m == 2) ? 64 * SAH * 4 : 0);
        float acc[2][4][4];
#pragma unroll
        for (int ma = 0; ma < 2; ma++)
#pragma unroll
            for (int nf = 0; nf < 4; nf++)
#pragma unroll
                for (int e = 0; e < 4; e++) acc[ma][nf][e] = 0.f;

        const uint2* bp = g_wpackh + ((size_t)(wmat + m) * 8 * 16 + wn * 4) * 32 + lane;

#pragma unroll
        for (int ks = 0; ks < 8; ks++) {
            unsigned a[2][4];
#pragma unroll
            for (int ma = 0; ma < 2; ma++) {
                asm volatile(
                    "ldmatrix.sync.aligned.m8n8.x4.shared.b16 {%0,%1,%2,%3}, [%4];"
                    : "=r"(a[ma][0]), "=r"(a[ma][1]), "=r"(a[ma][2]), "=r"(a[ma][3])
                    : "r"(ab + ma * 16 * SAH * 4 + ks * 32));
            }
#pragma unroll
            for (int nf = 0; nf < 4; nf++) {
                uint2 bv = __ldg(bp + (ks * 16 + nf) * 32);
#pragma unroll
                for (int ma = 0; ma < 2; ma++) {
                    asm volatile(
                        "mma.sync.aligned.m16n8k16.row.col.f32.f16.f16.f32 "
                        "{%0,%1,%2,%3}, {%4,%5,%6,%7}, {%8,%9}, {%0,%1,%2,%3};"
                        : "+f"(acc[ma][nf][0]), "+f"(acc[ma][nf][1]),
                          "+f"(acc[ma][nf][2]), "+f"(acc[ma][nf][3])
                        : "r"(a[ma][0]), "r"(a[ma][1]), "r"(a[ma][2]), "r"(a[ma][3]),
                          "r"(bv.x), "r"(bv.y));
                }
            }
        }

        const float* bm = bias + m * D;
        void* OUT = (m == 0) ? O0 : (m == 1) ? O1 : O2;

        if (STAGED) {
            // ---- stage 1: accs (+bias) -> smem stage (conflict-free) ----
#pragma unroll
            for (int ma = 0; ma < 2; ma++) {
#pragma unroll
                for (int rr = 0; rr < 2; rr++) {
                    int row = wm * 32 + ma * 16 + g + rr * 8;
#pragma unroll
                    for (int nf = 0; nf < 4; nf++) {
                        int c = wn * 32 + nf * 8 + 2 * t4;
                        float2 bi = *(const float2*)(bm + c);
                        float vx = acc[ma][nf][rr * 2 + 0] + bi.x;
                        float vy = acc[ma][nf][rr * 2 + 1] + bi.y;
                        if (HOUT) {
                            __half2 hv = __floats2half2_rn(vx, vy);
                            stg[row * SAH + wn * 16 + nf * 4 + t4] = *(unsigned*)&hv;
                        } else {
                            float2* sf = (float2*)stg;
                            sf[row * 70 + wn * 16 + nf * 4 + t4] = make_float2(vx, vy);
                        }
                    }
                }
            }
            __syncthreads();

            // ---- stage 2: coalesced 16B row copies to global ----
            if (HOUT) {
#pragma unroll
                for (int it = 0; it < 4; it++) {
                    int idx = tid + it * 256;
                    int row = idx >> 4, q = idx & 15;
                    int r = tb + row;
                    if (r < ntok) {
                        int rowg = r;
                        if (SCATTER) rowg = (r < n16) ? s16[r] : s64[r - n16];
                        uint4 v = *(const uint4*)(stg + row * SAH + q * 4);
                        *(uint4*)((__half*)OUT + (size_t)rowg * D + q * 8) = v;
                    }
                }
            } else {
#pragma unroll
                for (int it = 0; it < 8; it++) {
                    int idx = tid + it * 256;
                    int row = idx >> 5, q = idx & 31;
                    int r = tb + row;
                    if (r < ntok) {
                        int rowg = r;
                        if (SCATTER) rowg = (r < n16) ? s16[r] : s64[r - n16];
                        uint4 v = *(const uint4*)((const float*)stg + row * 140 + q * 4);
                        *(uint4*)((float*)OUT + (size_t)rowg * D + q * 4) = v;
                    }
                }
            }
            if (m + 1 < NM) __syncthreads();   // stage reused next matrix
        } else {
            // ---- direct epilogue (round-12 proven path) ----
#pragma unroll
            for (int ma = 0; ma < 2; ma++) {
#pragma unroll
                for (int rr = 0; rr < 2; rr++) {
                    int r = tb + wm * 32 + ma * 16 + g + rr * 8;
                    if (r < ntok) {
                        int rowg = r;
                        if (SCATTER) rowg = (r < n16) ? s16[r] : s64[r - n16];
#pragma unroll
                        for (int nf = 0; nf < 4; nf++) {
                            int c = wn * 32 + nf * 8 + 2 * t4;
                            float2 bi = *(const float2*)(bm + c);
                            float vx = acc[ma][nf][rr * 2 + 0] + bi.x;
                            float vy = acc[ma][nf][rr * 2 + 1] + bi.y;
                            if (HOUT) {
                                __half* o = (__half*)OUT + (size_t)rowg * D;
                                *(__half2*)(o + c) = __floats2half2_rn(vx, vy);
                            } else {
                                float* o = (float*)OUT + (size_t)rowg * D;
                                *(float2*)(o + c) = make_float2(vx, vy);
                            }
                        }
                    }
                }
            }
        }
    }
}

// ---------------------------------------------------------------------------
__device__ __forceinline__ void h8_to_f(const uint4& u, float* f) {
    float2 a = __half22float2(*(const __half2*)&u.x); f[0] = a.x; f[1] = a.y;
    float2 b = __half22float2(*(const __half2*)&u.y); f[2] = b.x; f[3] = b.y;
    float2 c = __half22float2(*(const __half2*)&u.z); f[4] = c.x; f[5] = c.y;
    float2 d = __half22float2(*(const __half2*)&u.w); f[6] = d.x; f[7] = d.y;
}

// fp16 dot of 16 halves (two uint4 pairs), fp32 result
__device__ __forceinline__ float dot16h(const uint4& qa, const uint4& qb,
                                        const uint4& ka, const uint4& kb) {
    __half2 t = __hmul2(u2h(qa.x), u2h(ka.x));
    t = __hfma2(u2h(qa.y), u2h(ka.y), t);
    t = __hfma2(u2h(qa.z), u2h(ka.z), t);
    t = __hfma2(u2h(qa.w), u2h(ka.w), t);
    __half2 s = __hmul2(u2h(qb.x), u2h(kb.x));
    s = __hfma2(u2h(qb.y), u2h(kb.y), s);
    s = __hfma2(u2h(qb.z), u2h(kb.z), s);
    s = __hfma2(u2h(qb.w), u2h(kb.w), s);
    float2 f = __half22float2(__hadd2(t, s));
    return f.x + f.y;
}

// ---------------------------------------------------------------------------
// s16 attention: 2 queries/thread (round-12 proven).
// ---------------------------------------------------------------------------
template <int L, int TPB>
__global__ __launch_bounds__(TPB)
void attn2(const __half* __restrict__ Q, const __half* __restrict__ K,
           const __half* __restrict__ V, const int* __restrict__ ws,
           __half* __restrict__ AO, int nw)
{
    constexpr int QS  = L / 2;
    constexpr int TPW = QS * 8;
    constexpr int WPB = TPB / TPW;
    extern __shared__ uint4 smh[];
    const int tid = threadIdx.x;
    const int wl  = tid / TPW;
    const int w   = blockIdx.x * WPB + wl;
    uint4* Ks = smh + (size_t)wl * (2 * L * 16);
    uint4* Vs = Ks + L * 16;

    int t0 = 0, len = 0;
    if (w < nw) { t0 = ws[w]; len = ws[w + 1] - t0; }

    const int lt = tid - wl * TPW;
    for (int idx = lt; idx < len * 16; idx += TPW) {
        int j = idx >> 4, gg = idx & 15;
        int h = gg >> 1, p = gg & 1;
        Ks[j * 16 + (p * 8 + h)] = ((const uint4*)K)[(size_t)(t0 + j) * 16 + gg];
        Vs[j * 16 + (p * 8 + h)] = ((const uint4*)V)[(size_t)(t0 + j) * 16 + gg];
    }
    __syncthreads();

    const int qs = lt >> 3;
    const int h  = lt & 7;
    const int q0 = 2 * qs, q1 = 2 * qs + 1;
    if (w >= nw || q0 >= len) return;
    const bool v1 = (q1 < len);

    uint4 qa0, qb0, qa1, qb1;
    {
        const uint4* Qp0 = (const uint4*)Q + (size_t)(t0 + q0) * 16 + h * 2;
        const uint4* Qp1 = (const uint4*)Q + (size_t)(t0 + (v1 ? q1 : q0)) * 16 + h * 2;
        qa0 = Qp0[0]; qb0 = Qp0[1];
        qa1 = Qp1[0]; qb1 = Qp1[1];
    }

    float s0[L], s1[L];
    float m0 = -1e30f, m1 = -1e30f;
#pragma unroll
    for (int j = 0; j < L; j++) {
        bool kv = j < len;
        int key = kv ? j : 0;
        uint4 ka = Ks[key * 16 + h], kb = Ks[key * 16 + 8 + h];
        float a = dot16h(qa0, qb0, ka, kb);
        float b = dot16h(qa1, qb1, ka, kb);
        s0[j] = kv ? a : -1e30f;
        s1[j] = kv ? b : -1e30f;
        m0 = fmaxf(m0, s0[j]); m1 = fmaxf(m1, s1[j]);
    }
    float d0 = 0.f, d1 = 0.f;
    float acc0[16], acc1[16];
#pragma unroll
    for (int e = 0; e < 16; e++) { acc0[e] = 0.f; acc1[e] = 0.f; }
#pragma unroll
    for (int j = 0; j < L; j++) {
        if (j >= len) break;
        float p0 = __expf((s0[j] - m0) * 0.25f);
        float p1 = __expf((s1[j] - m1) * 0.25f);
        d0 += p0; d1 += p1;
        float vf[16];
        h8_to_f(Vs[j * 16 + h], vf); h8_to_f(Vs[j * 16 + 8 + h], vf + 8);
#pragma unroll
        for (int e = 0; e < 16; e++) {
            acc0[e] += p0 * vf[e];
            acc1[e] += p1 * vf[e];
        }
    }
    {
        float inv = 1.f / d0;
        __half2* o = (__half2*)(AO + (size_t)(t0 + q0) * D + h * 16);
#pragma unroll
        for (int e = 0; e < 8; e++)
            o[e] = __floats2half2_rn(acc0[2 * e] * inv, acc0[2 * e + 1] * inv);
    }
    if (v1) {
        float inv = 1.f / d1;
        __half2* o = (__half2*)(AO + (size_t)(t0 + q1) * D + h * 16);
#pragma unroll
        for (int e = 0; e < 8; e++)
            o[e] = __floats2half2_rn(acc1[2 * e] * inv, acc1[2 * e + 1] * inv);
    }
}

// ---------------------------------------------------------------------------
// s64 attention: 4 queries/thread, 8-key chunked online softmax, fp16 QK dot,
// fp32 PV accumulation. 1 window/block, 128 threads. (round-12 proven)
// ---------------------------------------------------------------------------
__global__ __launch_bounds__(128)
void attn4(const __half* __restrict__ Q, const __half* __restrict__ K,
           const __half* __restrict__ V, const int* __restrict__ ws,
           __half* __restrict__ AO, int nw)
{
    constexpr int L = 64;
    __shared__ uint4 smkv[2 * L * 16];   // 32 KB
    uint4* Ks = smkv;
    uint4* Vs = smkv + L * 16;
    const int w = blockIdx.x;
    const int t0 = ws[w];
    const int len = ws[w + 1] - t0;
    const int tid = threadIdx.x;

    for (int idx = tid; idx < len * 16; idx += 128) {
        int j = idx >> 4, gg = idx & 15;
        int h = gg >> 1, p = gg & 1;
        Ks[j * 16 + (p * 8 + h)] = ((const uint4*)K)[(size_t)(t0 + j) * 16 + gg];
        Vs[j * 16 + (p * 8 + h)] = ((const uint4*)V)[(size_t)(t0 + j) * 16 + gg];
    }
    __syncthreads();

    const int qs = tid >> 3;
    const int h  = tid & 7;
    const int q0 = 4 * qs;
    if (q0 >= len) return;
    const int nq = min(4, len - q0);

    uint4 qa[4], qb[4];
#pragma unroll
    for (int qi = 0; qi < 4; qi++) {
        int qq = q0 + (qi < nq ? qi : nq - 1);
        const uint4* Qp = (const uint4*)Q + (size_t)(t0 + qq) * 16 + h * 2;
        qa[qi] = Qp[0]; qb[qi] = Qp[1];
    }

    float m[4], d[4], acc[4][16];
#pragma unroll
    for (int qi = 0; qi < 4; qi++) {
        m[qi] = -1e30f; d[qi] = 0.f;
#pragma unroll
        for (int e = 0; e < 16; e++) acc[qi][e] = 0.f;
    }

    for (int c0 = 0; c0 < len; c0 += 8) {
        float s[4][8];
#pragma unroll
        for (int j = 0; j < 8; j++) {
            bool kv = (c0 + j) < len;
            int key = kv ? c0 + j : 0;
            uint4 ka = Ks[key * 16 + h], kb = Ks[key * 16 + 8 + h];
#pragma unroll
            for (int qi = 0; qi < 4; qi++)
                s[qi][j] = kv ? dot16h(qa[qi], qb[qi], ka, kb) : -1e30f;
        }
#pragma unroll
        for (int qi = 0; qi < 4; qi++) {
            float cm = s[qi][0];
#pragma unroll
            for (int j = 1; j < 8; j++) cm = fmaxf(cm, s[qi][j]);
            float mn = fmaxf(m[qi], cm);
            float sc = __expf((m[qi] - mn) * 0.25f);
            m[qi] = mn;
            d[qi] *= sc;
#pragma unroll
            for (int e = 0; e < 16; e++) acc[qi][e] *= sc;
        }
#pragma unroll
        for (int j = 0; j < 8; j++) {
            if (c0 + j >= len) break;
            float vf[16];
            h8_to_f(Vs[(c0 + j) * 16 + h], vf);
            h8_to_f(Vs[(c0 + j) * 16 + 8 + h], vf + 8);
            float p[4];
#pragma unroll
            for (int qi = 0; qi < 4; qi++) {
                p[qi] = __expf((s[qi][j] - m[qi]) * 0.25f);
                d[qi] += p[qi];
            }
#pragma unroll
            for (int e = 0; e < 16; e++) {
#pragma unroll
                for (int qi = 0; qi < 4; qi++)
                    acc[qi][e] += p[qi] * vf[e];
            }
        }
    }

#pragma unroll
    for (int qi = 0; qi < 4; qi++) {
        if (qi >= nq) break;
        float inv = 1.f / d[qi];
        __half2* o = (__half2*)(AO + (size_t)(t0 + q0 + qi) * D + h * 16);
#pragma unroll
        for (int e = 0; e < 8; e++)
            o[e] = __floats2half2_rn(acc[qi][2 * e] * inv, acc[qi][2 * e + 1] * inv);
    }
}

// ---------------------------------------------------------------------------
extern "C" void kernel_launch(void* const* d_in, const int* in_sizes, int n_in,
                              void* d_out, int out_size)
{
    const float* feat  = (const float*)d_in[0];
    const float* pos16 = (const float*)d_in[1];
    const float* pos64 = (const float*)d_in[2];
    const float* Win   = (const float*)d_in[3];
    const float* bin   = (const float*)d_in[4];
    const float* Wout  = (const float*)d_in[5];
    const float* bout  = (const float*)d_in[6];
    const int* vox16 = (const int*)d_in[7];
    const int* fp16i = (const int*)d_in[8];
    const int* vox64 = (const int*)d_in[9];
    const int* fp64i = (const int*)d_in[10];
    const int n16  = in_sizes[7];
    const int n64  = in_sizes[9];
    const int nw16 = in_sizes[1] / (16 * D);
    const int nw64 = in_sizes[2] / (64 * D);
    const int ntok = n16 + n64;
    float* out = (float*)d_out;

    float* scr = nullptr;
    cudaGetSymbolAddress((void**)&scr, g_scr);
    int* ws16 = nullptr; cudaGetSymbolAddress((void**)&ws16, g_ws16);
    int* ws64 = nullptr; cudaGetSymbolAddress((void**)&ws64, g_ws64);
    __half* Qh = (__half*)scr;
    __half* Kh = Qh + (size_t)NMAX * D;
    __half* Vh = Qh + (size_t)2 * NMAX * D;
    __half* AO = Qh + (size_t)3 * NMAX * D;

    const size_t ATILE = (size_t)64 * SAH * sizeof(unsigned);       // 17408
    const size_t gsm3  = 3 * ATILE;                                 // QKV: 2 tiles + fp16 stage
    const size_t psm   = ATILE;                                     // proj: 1 tile
    const size_t asm16 = (size_t)4 * 2 * 16 * 16 * sizeof(uint4);   // 32 KB
    cudaFuncSetAttribute((const void*)gemm_mma<true, 3, true, false, false, true, true>,
                         cudaFuncAttributeMaxDynamicSharedMemorySize, (int)gsm3);
    cudaFuncSetAttribute((const void*)gemm_mma<false, 1, false, true, true, false, false>,
                         cudaFuncAttributeMaxDynamicSharedMemorySize, (int)psm);
    cudaFuncSetAttribute((const void*)attn2<16, 256>,
                         cudaFuncAttributeMaxDynamicSharedMemorySize, (int)asm16);

    build_ws2<<<(ntok + 255) / 256, 256>>>(fp16i, n16, nw16, ws16,
                                           fp64i, n64, nw64, ws64);
    pack_w<<<64, 256>>>(Win, Wout);

    const int gt = (ntok + 63) / 64;
    const size_t off = (size_t)n16 * D;

    // Fused Q+K+V over BOTH groups: one gather, three matrices, fp16 outputs,
    // staged coalesced epilogue.
    gemm_mma<true, 3, true, false, false, true, true><<<gt, 256, gsm3>>>(
        feat, vox16, vox64, pos16, pos64, fp16i, fp64i, 0, bin,
        Qh, Kh, Vh, nullptr, nullptr, n16, ntok);

    // Attention (proven round-12 kernels).
    attn2<16, 256><<<(nw16 + 3) / 4, 256, asm16>>>(Qh, Kh, Vh, ws16, AO, nw16);
    attn4<<<nw64, 128>>>(Qh + off, Kh + off, Vh + off, ws64, AO + off, nw64);

    // Output projection (fp16 in, fp32 out, direct epilogue), scattered into d_out.
    gemm_mma<false, 1, false, true, true, false, false><<<gt, 256, psm>>>(
        AO, nullptr, nullptr, nullptr, nullptr, nullptr, nullptr, 3, bout,
        out, nullptr, nullptr, vox16, vox64, n16, ntok);
}